// round 2
// baseline (speedup 1.0000x reference)
#include <cuda_runtime.h>
#include <cuda_bf16.h>

// ---------------------------------------------------------------------------
// Fused single-kernel DetectionLoss (YOLOv5-style).
//   p3 [16,3,80,80,85] p4 [16,3,40,40,85] p5 [16,3,20,20,85]
//   boxes [16,64,4] xyxy, labels [16,64] i32, valid [16,64] bool, anchors[3,3,2]
// Output: scalar f32.
//
// BCE(x,t) = softplus(x) - x*t  =>
//   obj_l = ( sum_all softplus(x4) - sum_{unique pos cells} x4 ) / Ncells_l
// Grid layout: blocks 0..2 = per-layer positives (1024 boxes each, smem-hash
// dedup); blocks 3..101 = obj softplus sweep (4096 cells each); last block to
// finish finalizes + resets accumulators (self-cleaning for graph replay).
// ---------------------------------------------------------------------------

#define B_    16
#define M_    64
#define A_    3
#define NC_   80
#define CH_   85
#define NBOX  (B_ * M_)               // 1024
#define CELLS0 (B_ * A_ * 80 * 80)    // 307200
#define CELLS1 (B_ * A_ * 40 * 40)    // 76800
#define CELLS2 (B_ * A_ * 20 * 20)    // 19200
#define CELLS_TOTAL (CELLS0 + CELLS1 + CELLS2)   // 403200

#define CELLS_PER_OBJ_BLOCK 4096
#define OBJ_BLOCKS ((CELLS_TOTAL + CELLS_PER_OBJ_BLOCK - 1) / CELLS_PER_OBJ_BLOCK)  // 99
#define TOTAL_BLOCKS (3 + OBJ_BLOCKS)   // 102
#define HASH_SZ 2048

static __device__ double g_sp[3];     // sum softplus(x4), whole grid
static __device__ double g_negx[3];   // - sum x4 over unique positive cells
static __device__ double g_cls[3];
static __device__ double g_box[3];
static __device__ int    g_npos[3];
static __device__ unsigned int g_done; // completion counter (reset by finalize)

__device__ __forceinline__ float softplusf(float x) {
    return fmaxf(x, 0.0f) + log1pf(expf(-fabsf(x)));
}

__global__ void __launch_bounds__(1024, 1)
dl_fused_kernel(const float* __restrict__ p3,
                const float* __restrict__ p4,
                const float* __restrict__ p5,
                const float* __restrict__ boxes,
                const int*   __restrict__ labels,
                const unsigned char* __restrict__ valid,
                const float* __restrict__ anchors,
                float* __restrict__ out) {
    const int tid = threadIdx.x;

    if (blockIdx.x < 3) {
        // ================= positives path: one block per layer ==============
        __shared__ int    s_hash[HASH_SZ];
        __shared__ double s_cls, s_box, s_negx;
        __shared__ int    s_npos;

        s_hash[tid] = -1;
        s_hash[tid + 1024] = -1;
        if (tid == 0) { s_cls = 0.0; s_box = 0.0; s_negx = 0.0; s_npos = 0; }
        __syncthreads();

        const int layer = blockIdx.x;
        const int i = tid;                 // box index: b*M + m
        const int b = i >> 6;
        const int g = 80 >> layer;

        const float* P = (layer == 0) ? p3 : (layer == 1) ? p4 : p5;

        const float x1 = boxes[i * 4 + 0];
        const float y1 = boxes[i * 4 + 1];
        const float x2 = boxes[i * 4 + 2];
        const float y2 = boxes[i * 4 + 3];
        const float gf = (float)g;
        const float cx = (x1 + x2) * 0.5f * gf;
        const float cy = (y1 + y2) * 0.5f * gf;
        const float w  = (x2 - x1) * gf;
        const float h  = (y2 - y1) * gf;

        // wh-IoU vs layer anchors; first-max argmax (strict >)
        float best = -1.0f; int ba = 0;
#pragma unroll
        for (int a = 0; a < A_; a++) {
            const float aw = anchors[layer * 6 + a * 2 + 0];
            const float ah = anchors[layer * 6 + a * 2 + 1];
            const float inter = fminf(w, aw) * fminf(h, ah);
            const float uni   = w * h + aw * ah - inter;
            const float iou   = inter / (uni + 1e-6f);
            if (iou > best) { best = iou; ba = a; }
        }

        const bool pos = valid[i] && (best > 0.5f);

        if (pos) {
            int gx = (int)cx; gx = min(max(gx, 0), g - 1);
            int gy = (int)cy; gy = min(max(gy, 0), g - 1);
            const int  cell = ((b * A_ + ba) * g + gy) * g + gx;
            const long base = (long)cell * CH_;

            atomicAdd(&s_npos, 1);

            // ---- cls: sum_c softplus(x_c) - x_label ------------------------
            const int lab = labels[i];
            float cl = 0.0f;
#pragma unroll 4
            for (int c = 0; c < NC_; c++) cl += softplusf(__ldg(&P[base + 5 + c]));
            cl -= __ldg(&P[base + 5 + lab]);
            atomicAdd(&s_cls, (double)cl);

            // ---- bbox: CIoU loss (reference epsilons) ----------------------
            const float pcx0 = P[base + 0], pcy0 = P[base + 1];
            const float pw   = P[base + 2], ph   = P[base + 3];
            const float px1 = pcx0 - pw * 0.5f, py1 = pcy0 - ph * 0.5f;
            const float px2 = pcx0 + pw * 0.5f, py2 = pcy0 + ph * 0.5f;
            const float tx1 = cx - w * 0.5f, ty1 = cy - h * 0.5f;
            const float tx2 = cx + w * 0.5f, ty2 = cy + h * 0.5f;

            const float ix1 = fmaxf(px1, tx1), iy1 = fmaxf(py1, ty1);
            const float ix2 = fminf(px2, tx2), iy2 = fminf(py2, ty2);
            const float inter = fmaxf(ix2 - ix1, 0.0f) * fmaxf(iy2 - iy1, 0.0f);
            const float a1 = (px2 - px1) * (py2 - py1);
            const float a2 = (tx2 - tx1) * (ty2 - ty1);
            const float iou = inter / (a1 + a2 - inter + 1e-7f);

            const float pcx = (px1 + px2) * 0.5f, pcy = (py1 + py2) * 0.5f;
            const float tcx = (tx1 + tx2) * 0.5f, tcy = (ty1 + ty2) * 0.5f;
            const float cd  = (pcx - tcx) * (pcx - tcx) + (pcy - tcy) * (pcy - tcy);

            const float ex1 = fminf(px1, tx1), ey1 = fminf(py1, ty1);
            const float ex2 = fmaxf(px2, tx2), ey2 = fmaxf(py2, ty2);
            const float dd  = (ex2 - ex1) * (ex2 - ex1) + (ey2 - ey1) * (ey2 - ey1);

            atomicAdd(&s_box, (double)(1.0f - (iou - cd / (dd + 1e-7f))));

            // ---- dedup unique cells via smem hash, sum -x4 -----------------
            unsigned int hsh = ((unsigned int)cell * 2654435761u) >> 20;
            hsh &= (HASH_SZ - 1);
            bool owner = false;
            for (;;) {
                int old = atomicCAS(&s_hash[hsh], -1, cell);
                if (old == -1) { owner = true; break; }
                if (old == cell) break;               // duplicate
                hsh = (hsh + 1) & (HASH_SZ - 1);
            }
            if (owner) atomicAdd(&s_negx, -(double)P[base + 4]);
        }
        __syncthreads();
        if (tid == 0) {
            g_cls[layer]  = s_cls;
            g_box[layer]  = s_box;
            g_negx[layer] = s_negx;
            g_npos[layer] = s_npos;
        }
    } else {
        // ================= obj softplus sweep ===============================
        __shared__ float s_obj[3];
        if (tid < 3) s_obj[tid] = 0.0f;
        __syncthreads();

        const int o = blockIdx.x - 3;
        float acc0 = 0.0f, acc1 = 0.0f, acc2 = 0.0f;
#pragma unroll
        for (int k = 0; k < 4; k++) {
            const int idx = o * CELLS_PER_OBJ_BLOCK + k * 1024 + tid;
            if (idx < CELLS_TOTAL) {
                float v;
                if (idx < CELLS0) {
                    v = softplusf(__ldg(&p3[(long)idx * CH_ + 4]));
                    acc0 += v;
                } else if (idx < CELLS0 + CELLS1) {
                    v = softplusf(__ldg(&p4[(long)(idx - CELLS0) * CH_ + 4]));
                    acc1 += v;
                } else {
                    v = softplusf(__ldg(&p5[(long)(idx - CELLS0 - CELLS1) * CH_ + 4]));
                    acc2 += v;
                }
            }
        }
        // warp reduce the three lane sums, then shared atomics per warp
#pragma unroll
        for (int s = 16; s > 0; s >>= 1) {
            acc0 += __shfl_down_sync(0xFFFFFFFFu, acc0, s);
            acc1 += __shfl_down_sync(0xFFFFFFFFu, acc1, s);
            acc2 += __shfl_down_sync(0xFFFFFFFFu, acc2, s);
        }
        if ((tid & 31) == 0) {
            if (acc0 != 0.0f) atomicAdd(&s_obj[0], acc0);
            if (acc1 != 0.0f) atomicAdd(&s_obj[1], acc1);
            if (acc2 != 0.0f) atomicAdd(&s_obj[2], acc2);
        }
        __syncthreads();
        if (tid < 3 && s_obj[tid] != 0.0f)
            atomicAdd(&g_sp[tid], (double)s_obj[tid]);
    }

    // ================= completion + inline finalize =========================
    __shared__ bool amLast;
    __threadfence();
    __syncthreads();
    if (tid == 0)
        amLast = (atomicAdd(&g_done, 1u) == (unsigned)(TOTAL_BLOCKS - 1));
    __syncthreads();

    if (amLast && tid == 0) {
        const double ncell[3] = {(double)CELLS0, (double)CELLS1, (double)CELLS2};
        double cls = 0.0, obj = 0.0, box = 0.0;
#pragma unroll
        for (int l = 0; l < 3; l++) {
            const int np = g_npos[l];
            if (np > 0) {
                const double denom = (double)np;     // np>=1 so max(np,1)=np
                cls += g_cls[l] / (denom * (double)NC_);
                obj += (g_sp[l] + g_negx[l]) / ncell[l];
                box += g_box[l] / denom;
            }
        }
        out[0] = (float)(0.5 * cls + 1.0 * obj + 0.05 * box);
        // self-reset for next graph replay
#pragma unroll
        for (int l = 0; l < 3; l++) {
            g_sp[l] = 0.0; g_negx[l] = 0.0; g_cls[l] = 0.0; g_box[l] = 0.0;
            g_npos[l] = 0;
        }
        __threadfence();
        g_done = 0u;
    }
}

extern "C" void kernel_launch(void* const* d_in, const int* in_sizes, int n_in,
                              void* d_out, int out_size) {
    const float*         p3      = (const float*)d_in[0];
    const float*         p4      = (const float*)d_in[1];
    const float*         p5      = (const float*)d_in[2];
    const float*         boxes   = (const float*)d_in[3];
    const int*           labels  = (const int*)d_in[4];
    const unsigned char* valid   = (const unsigned char*)d_in[5];
    const float*         anchors = (const float*)d_in[6];
    float*               out     = (float*)d_out;

    dl_fused_kernel<<<TOTAL_BLOCKS, 1024>>>(p3, p4, p5, boxes, labels, valid,
                                            anchors, out);
}